// round 5
// baseline (speedup 1.0000x reference)
#include <cuda_runtime.h>

// Problem constants
#define B_  32
#define D_  64
#define L_  8192
#define K_  512
#define N_  (B_ * L_)          // 262144 rows
#define BDL (B_ * D_ * L_)     // 16777216

// Output packing (flattened f32, reference tuple order):
//   [0, BDL)            out  [B, D, L]
//   [BDL]               loss
//   [BDL+1]             perplexity
//   [BDL+2, +K*D)       weight passthrough   (byte offset 8 mod 16!)
//   [.., +N)            encoding_indices
#define OFF_OUT   0
#define OFF_LOSS  (BDL)
#define OFF_PERP  (BDL + 1)
#define OFF_W     (BDL + 2)
#define OFF_IDX   (BDL + 2 + K_ * D_)

#define SMEM_BYTES ((K_ * D_ + K_) * (int)sizeof(float))

__device__ double g_loss;
__device__ int    g_used[K_];

// ---------------------------------------------------------------------------
// Init: zero accumulators, copy weight passthrough into the output buffer.
// out + OFF_W is only 8-byte aligned (OFF_W*4 = 8 mod 16) -> use float2.
// ---------------------------------------------------------------------------
__global__ void vq_init(const float* __restrict__ w, float* __restrict__ out) {
    int i = blockIdx.x * blockDim.x + threadIdx.x;
    if (i < K_ * D_ / 2) {
        reinterpret_cast<float2*>(out + OFF_W)[i] =
            reinterpret_cast<const float2*>(w)[i];
    }
    if (i < K_) g_used[i] = 0;
    if (i == 0) g_loss = 0.0;
}

// ---------------------------------------------------------------------------
// Main: per-thread row, codebook in smem, packed f32x2 FMA inner loop.
// ---------------------------------------------------------------------------
extern __shared__ float smem[];

__global__ void __launch_bounds__(256, 1)
vq_main(const float* __restrict__ x, const float* __restrict__ w,
        float* __restrict__ out) {
    float* sw  = smem;              // [K_][D_]
    float* sw2 = smem + K_ * D_;    // [K_] code squared norms

    // Cooperative codebook load (vectorized; w base is 16B-aligned)
    for (int i = threadIdx.x; i < K_ * D_ / 4; i += 256)
        reinterpret_cast<float4*>(sw)[i] = reinterpret_cast<const float4*>(w)[i];
    __syncthreads();

    // Code norms
    for (int j = threadIdx.x; j < K_; j += 256) {
        float s = 0.0f;
        const float* wj = sw + j * D_;
        #pragma unroll 8
        for (int d = 0; d < D_; d++) s = fmaf(wj[d], wj[d], s);
        sw2[j] = s;
    }
    __syncthreads();

    int n = blockIdx.x * 256 + threadIdx.x;    // row id = b*L + l
    int b = n >> 13;
    int l = n & (L_ - 1);
    const float* xp = x + (size_t)b * (D_ * L_) + l;

    // Load row [d-strided by L], pack pairs for f32x2
    unsigned long long xr2[D_ / 2];
    float x2 = 0.0f;
    #pragma unroll
    for (int d = 0; d < D_; d += 2) {
        float a = xp[(size_t)d * L_];
        float c = xp[(size_t)(d + 1) * L_];
        float2 p = make_float2(a, c);
        xr2[d / 2] = *reinterpret_cast<unsigned long long*>(&p);
        x2 = fmaf(a, a, x2);
        x2 = fmaf(c, c, x2);
    }

    float best = 3.4e38f;
    int   bi   = 0;

    #pragma unroll 2
    for (int j = 0; j < K_; j++) {
        const ulonglong2* wj = reinterpret_cast<const ulonglong2*>(sw + j * D_);
        unsigned long long a0 = 0ull, a1 = 0ull;   // two packed f32x2 accumulators
        #pragma unroll
        for (int i = 0; i < D_ / 4; i++) {
            ulonglong2 wv = wj[i];
            asm("fma.rn.f32x2 %0, %1, %2, %0;" : "+l"(a0)
                : "l"(xr2[2 * i]),     "l"(wv.x));
            asm("fma.rn.f32x2 %0, %1, %2, %0;" : "+l"(a1)
                : "l"(xr2[2 * i + 1]), "l"(wv.y));
        }
        unsigned long long as;
        asm("add.rn.f32x2 %0, %1, %2;" : "=l"(as) : "l"(a0), "l"(a1));
        float2 sf  = *reinterpret_cast<float2*>(&as);
        float  dot = sf.x + sf.y;
        // Mirror reference rounding: t1 = fl(x2 + w2); d = fl(t1 - 2*dot)
        // (2*dot exact; fmaf(-2,dot,t1) rounds once, same as the subtract)
        float t1   = x2 + sw2[j];
        float dist = fmaf(-2.0f, dot, t1);
        if (dist < best) { best = dist; bi = j; }   // strict <: first-index tie-break
    }

    // ---- outputs ----
    out[OFF_IDX + n] = (float)bi;
    g_used[bi] = 1;

    float* op = out + (size_t)b * (D_ * L_) + l;
    const float* wq = sw + bi * D_;
    float lsum = 0.0f;
    #pragma unroll
    for (int d = 0; d < D_; d += 2) {
        float2 p = *reinterpret_cast<float2*>(&xr2[d / 2]);
        float q0 = wq[d], q1 = wq[d + 1];
        op[(size_t)d * L_]       = q0;
        op[(size_t)(d + 1) * L_] = q1;
        float e0 = q0 - p.x, e1 = q1 - p.y;
        lsum = fmaf(e0, e0, lsum);
        lsum = fmaf(e1, e1, lsum);
    }
    // warp reduce then one double atomic per warp
    #pragma unroll
    for (int o = 16; o; o >>= 1)
        lsum += __shfl_xor_sync(0xffffffffu, lsum, o);
    if ((threadIdx.x & 31) == 0) atomicAdd(&g_loss, (double)lsum);
}

// ---------------------------------------------------------------------------
// Final: perplexity (count of used codes) and loss scalar.
// loss = q_latent + 0.1 * e_latent, both equal mean((q - x)^2) -> 1.1 * mse
// ---------------------------------------------------------------------------
__global__ void vq_fin(float* __restrict__ out) {
    __shared__ int cnt[16];
    int t = threadIdx.x;              // K_ = 512 threads
    int v = (t < K_) ? g_used[t] : 0;
    #pragma unroll
    for (int o = 16; o; o >>= 1) v += __shfl_xor_sync(0xffffffffu, v, o);
    if ((t & 31) == 0) cnt[t >> 5] = v;
    __syncthreads();
    if (t < 32) {
        int c = (t < 16) ? cnt[t] : 0;
        #pragma unroll
        for (int o = 8; o; o >>= 1) c += __shfl_xor_sync(0xffffffffu, c, o);
        if (t == 0) {
            out[OFF_PERP] = (float)c;
            out[OFF_LOSS] = (float)(1.1 * g_loss / (double)BDL);
        }
    }
}

// ---------------------------------------------------------------------------
extern "C" void kernel_launch(void* const* d_in, const int* in_sizes, int n_in,
                              void* d_out, int out_size) {
    // metadata order: x [B*D*L], weight [K*D]; be defensive about ordering.
    const float* x = (const float*)d_in[0];
    const float* w = (const float*)d_in[1];
    if (n_in >= 2 && in_sizes[0] == K_ * D_ && in_sizes[1] == BDL) {
        const float* t = x; x = w; w = t;
    }
    float* out = (float*)d_out;

    cudaFuncSetAttribute(vq_main, cudaFuncAttributeMaxDynamicSharedMemorySize,
                         SMEM_BYTES);

    vq_init<<<(K_ * D_ / 2 + 255) / 256, 256>>>(w, out);
    vq_main<<<N_ / 256, 256, SMEM_BYTES>>>(x, w, out);
    vq_fin<<<1, K_>>>(out);
}

// round 6
// speedup vs baseline: 1.2004x; 1.2004x over previous
#include <cuda_runtime.h>

// Problem constants
#define B_  32
#define D_  64
#define L_  8192
#define K_  512
#define N_  (B_ * L_)          // 262144 rows
#define BDL (B_ * D_ * L_)     // 16777216

// Output packing (flattened f32, reference tuple order)
#define OFF_OUT   0
#define OFF_LOSS  (BDL)
#define OFF_PERP  (BDL + 1)
#define OFF_W     (BDL + 2)
#define OFF_IDX   (BDL + 2 + K_ * D_)

#define SMEM_BYTES ((K_ * D_ + K_) * (int)sizeof(float))

typedef unsigned long long ull;

__device__ double g_loss;
__device__ int    g_used[K_];

// ---------------------------------------------------------------------------
// Init: zero accumulators, weight passthrough (out+OFF_W only 8B aligned).
// ---------------------------------------------------------------------------
__global__ void vq_init(const float* __restrict__ w, float* __restrict__ out) {
    int i = blockIdx.x * blockDim.x + threadIdx.x;
    if (i < K_ * D_ / 2) {
        reinterpret_cast<float2*>(out + OFF_W)[i] =
            reinterpret_cast<const float2*>(w)[i];
    }
    if (i < K_) g_used[i] = 0;
    if (i == 0) g_loss = 0.0;
}

// ---------------------------------------------------------------------------
// Main: 2 rows per thread, codebook in smem, 4 packed-f32x2 FMA chains.
// ---------------------------------------------------------------------------
extern __shared__ float smem[];

__global__ void __launch_bounds__(256, 1)
vq_main(const float* __restrict__ x, const float* __restrict__ w,
        float* __restrict__ out) {
    float* sw  = smem;              // [K_][D_]
    float* sw2 = smem + K_ * D_;    // [K_]

    for (int i = threadIdx.x; i < K_ * D_ / 4; i += 256)
        reinterpret_cast<float4*>(sw)[i] = reinterpret_cast<const float4*>(w)[i];
    __syncthreads();

    for (int j = threadIdx.x; j < K_; j += 256) {
        float s = 0.0f;
        const float* wj = sw + j * D_;
        #pragma unroll 8
        for (int d = 0; d < D_; d++) s = fmaf(wj[d], wj[d], s);
        sw2[j] = s;
    }
    __syncthreads();

    // Two rows per thread: na = blk*512 + tid, nb = na + 256
    int na = blockIdx.x * 512 + threadIdx.x;
    int nb = na + 256;
    int ba = na >> 13, la = na & (L_ - 1);
    int bb = nb >> 13, lb = nb & (L_ - 1);
    const float* xpa = x + (size_t)ba * (D_ * L_) + la;
    const float* xpb = x + (size_t)bb * (D_ * L_) + lb;

    ull xa[D_ / 2], xb[D_ / 2];
    float x2a = 0.0f, x2b = 0.0f;
    #pragma unroll
    for (int d = 0; d < D_; d += 2) {
        float a0 = xpa[(size_t)d * L_], a1 = xpa[(size_t)(d + 1) * L_];
        float b0 = xpb[(size_t)d * L_], b1 = xpb[(size_t)(d + 1) * L_];
        float2 pa = make_float2(a0, a1);
        float2 pb = make_float2(b0, b1);
        xa[d / 2] = *reinterpret_cast<ull*>(&pa);
        xb[d / 2] = *reinterpret_cast<ull*>(&pb);
        x2a = fmaf(a0, a0, x2a); x2a = fmaf(a1, a1, x2a);
        x2b = fmaf(b0, b0, x2b); x2b = fmaf(b1, b1, x2b);
    }

    float bestA = 3.4e38f, bestB = 3.4e38f;
    int   biA = 0, biB = 0;

    #pragma unroll 2
    for (int j = 0; j < K_; j++) {
        const ulonglong2* wj = reinterpret_cast<const ulonglong2*>(sw + j * D_);
        ull a0 = 0ull, a1 = 0ull, b0 = 0ull, b1 = 0ull;  // 4 chains
        #pragma unroll
        for (int i = 0; i < D_ / 4; i++) {
            ulonglong2 wv = wj[i];
            asm("fma.rn.f32x2 %0, %1, %2, %0;" : "+l"(a0)
                : "l"(xa[2 * i]),     "l"(wv.x));
            asm("fma.rn.f32x2 %0, %1, %2, %0;" : "+l"(a1)
                : "l"(xa[2 * i + 1]), "l"(wv.y));
            asm("fma.rn.f32x2 %0, %1, %2, %0;" : "+l"(b0)
                : "l"(xb[2 * i]),     "l"(wv.x));
            asm("fma.rn.f32x2 %0, %1, %2, %0;" : "+l"(b1)
                : "l"(xb[2 * i + 1]), "l"(wv.y));
        }
        ull sa, sb;
        asm("add.rn.f32x2 %0, %1, %2;" : "=l"(sa) : "l"(a0), "l"(a1));
        asm("add.rn.f32x2 %0, %1, %2;" : "=l"(sb) : "l"(b0), "l"(b1));
        float2 fa = *reinterpret_cast<float2*>(&sa);
        float2 fb = *reinterpret_cast<float2*>(&sb);
        float dotA = fa.x + fa.y;
        float dotB = fb.x + fb.y;
        // Mirror reference rounding: t1 = fl(x2 + w2); d = fl(t1 - 2*dot)
        float w2 = sw2[j];
        float dA = fmaf(-2.0f, dotA, x2a + w2);
        float dB = fmaf(-2.0f, dotB, x2b + w2);
        if (dA < bestA) { bestA = dA; biA = j; }   // strict <: first-index ties
        if (dB < bestB) { bestB = dB; biB = j; }
    }

    // ---- outputs ----
    out[OFF_IDX + na] = (float)biA;
    out[OFF_IDX + nb] = (float)biB;
    g_used[biA] = 1;
    g_used[biB] = 1;

    float* opa = out + (size_t)ba * (D_ * L_) + la;
    float* opb = out + (size_t)bb * (D_ * L_) + lb;
    const float* wqa = sw + biA * D_;
    const float* wqb = sw + biB * D_;
    float lsum = 0.0f;
    #pragma unroll
    for (int d = 0; d < D_; d += 2) {
        float2 pa = *reinterpret_cast<float2*>(&xa[d / 2]);
        float2 pb = *reinterpret_cast<float2*>(&xb[d / 2]);
        float qa0 = wqa[d], qa1 = wqa[d + 1];
        float qb0 = wqb[d], qb1 = wqb[d + 1];
        opa[(size_t)d * L_]       = qa0;
        opa[(size_t)(d + 1) * L_] = qa1;
        opb[(size_t)d * L_]       = qb0;
        opb[(size_t)(d + 1) * L_] = qb1;
        float e;
        e = qa0 - pa.x; lsum = fmaf(e, e, lsum);
        e = qa1 - pa.y; lsum = fmaf(e, e, lsum);
        e = qb0 - pb.x; lsum = fmaf(e, e, lsum);
        e = qb1 - pb.y; lsum = fmaf(e, e, lsum);
    }
    #pragma unroll
    for (int o = 16; o; o >>= 1)
        lsum += __shfl_xor_sync(0xffffffffu, lsum, o);
    if ((threadIdx.x & 31) == 0) atomicAdd(&g_loss, (double)lsum);
}

// ---------------------------------------------------------------------------
// Final: perplexity + loss scalar (1.1 * mse).
// ---------------------------------------------------------------------------
__global__ void vq_fin(float* __restrict__ out) {
    __shared__ int cnt[16];
    int t = threadIdx.x;              // K_ = 512 threads
    int v = (t < K_) ? g_used[t] : 0;
    #pragma unroll
    for (int o = 16; o; o >>= 1) v += __shfl_xor_sync(0xffffffffu, v, o);
    if ((t & 31) == 0) cnt[t >> 5] = v;
    __syncthreads();
    if (t < 32) {
        int c = (t < 16) ? cnt[t] : 0;
        #pragma unroll
        for (int o = 8; o; o >>= 1) c += __shfl_xor_sync(0xffffffffu, c, o);
        if (t == 0) {
            out[OFF_PERP] = (float)c;
            out[OFF_LOSS] = (float)(1.1 * g_loss / (double)BDL);
        }
    }
}

// ---------------------------------------------------------------------------
extern "C" void kernel_launch(void* const* d_in, const int* in_sizes, int n_in,
                              void* d_out, int out_size) {
    const float* x = (const float*)d_in[0];
    const float* w = (const float*)d_in[1];
    if (n_in >= 2 && in_sizes[0] == K_ * D_ && in_sizes[1] == BDL) {
        const float* t = x; x = w; w = t;
    }
    float* out = (float*)d_out;

    cudaFuncSetAttribute(vq_main, cudaFuncAttributeMaxDynamicSharedMemorySize,
                         SMEM_BYTES);

    vq_init<<<(K_ * D_ / 2 + 255) / 256, 256>>>(w, out);
    vq_main<<<N_ / 512, 256, SMEM_BYTES>>>(x, w, out);
    vq_fin<<<1, K_>>>(out);
}